// round 8
// baseline (speedup 1.0000x reference)
#include <cuda_runtime.h>
#include <cuda_fp16.h>
#include <cstdint>

#define BB 16
#define TT 1024
#define HH 256
#define LL 2048
#define MQ 64
#define TCHK 64
#define NCHUNK 16
#define NTHR 512

// smem pitches (halves); byte stride = odd multiple of 16B -> conflict-free ldsm
#define QP 264
#define XP 264
#define ECP 72
#define XCHB (TCHK * XP * 2)     // 33792 B per X buffer
#define ECB  (MQ * ECP * 2)      // 9216 B per E buffer

// smem byte offsets
#define SO_RS4  0                         // float rs4[2][64]
#define SO_INV  512                       // float inv[64]
#define SO_FLAG 768
#define SO_Q    1024                      // 64*264*2 = 33792
#define SO_X0   (SO_Q + 33792)            // 3 X buffers
#define SO_EC   (SO_X0 + 3 * XCHB)        // 2 E buffers
#define SMEM_BYTES (SO_EC + 2 * ECB)      // 154624 B

// named barrier ids: 1..3 = XR (B->A, X buf ready), 4..5 = EcFull (A->B),
// 6..7 = EcFree (B->A), 8 = A-internal, 9 = B-internal (X reads drained),
// 10/11 = join barriers
__device__ __half g_Xh[(size_t)BB * TT * HH];

__device__ __forceinline__ uint32_t smem_u32(const void* p) {
    uint32_t a;
    asm("{ .reg .u64 t; cvta.to.shared.u64 t, %1; cvt.u32.u64 %0, t; }" : "=r"(a) : "l"(p));
    return a;
}
__device__ __forceinline__ void bar_sync(int id, int cnt) {
    asm volatile("bar.sync %0, %1;" :: "r"(id), "r"(cnt) : "memory");
}
__device__ __forceinline__ void bar_arrive(int id, int cnt) {
    asm volatile("bar.arrive %0, %1;" :: "r"(id), "r"(cnt) : "memory");
}
__device__ __forceinline__ void ldsm4(uint32_t a, uint32_t* r) {
    asm volatile("ldmatrix.sync.aligned.m8n8.x4.shared.b16 {%0,%1,%2,%3}, [%4];"
                 : "=r"(r[0]), "=r"(r[1]), "=r"(r[2]), "=r"(r[3]) : "r"(a));
}
__device__ __forceinline__ void ldsm4t(uint32_t a, uint32_t* r) {
    asm volatile("ldmatrix.sync.aligned.m8n8.x4.trans.shared.b16 {%0,%1,%2,%3}, [%4];"
                 : "=r"(r[0]), "=r"(r[1]), "=r"(r[2]), "=r"(r[3]) : "r"(a));
}
__device__ __forceinline__ void mma16816(float* d, const uint32_t* a, const uint32_t* b) {
    asm volatile("mma.sync.aligned.m16n8k16.row.col.f32.f16.f16.f32 "
                 "{%0,%1,%2,%3}, {%4,%5,%6,%7}, {%8,%9}, {%0,%1,%2,%3};"
                 : "+f"(d[0]), "+f"(d[1]), "+f"(d[2]), "+f"(d[3])
                 : "r"(a[0]), "r"(a[1]), "r"(a[2]), "r"(a[3]), "r"(b[0]), "r"(b[1]));
}
__device__ __forceinline__ void cpasync16(uint32_t sa, const void* ga) {
    asm volatile("cp.async.ca.shared.global [%0], [%1], 16;" :: "r"(sa), "l"(ga));
}
#define CP_COMMIT()  asm volatile("cp.async.commit_group;" ::: "memory")
#define CP_WAIT(n)   asm volatile("cp.async.wait_group %0;" :: "n"(n) : "memory")

// ---------------- X f32 -> fp16 convert ----------------
__global__ void __launch_bounds__(256)
xconv(const float* __restrict__ X)
{
    const size_t i = ((size_t)blockIdx.x * 256 + threadIdx.x) * 8;
    float4 a = *(const float4*)(X + i);
    float4 b = *(const float4*)(X + i + 4);
    half2 h[4] = { __floats2half2_rn(a.x, a.y), __floats2half2_rn(a.z, a.w),
                   __floats2half2_rn(b.x, b.y), __floats2half2_rn(b.z, b.w) };
    *(uint4*)(g_Xh + i) = *(uint4*)h;
}

// ---------------- warp-specialized fused kernel ----------------
__global__ void __launch_bounds__(NTHR, 1)
pla_ws(const void*  __restrict__ labels_raw, // (B,L) int32/int64
       const float* __restrict__ table,      // (C+1,H)
       float* __restrict__ logits,           // (B,L,H)
       float* __restrict__ att)              // (B,L,T)
{
    extern __shared__ char sm[];
    float*  rs4 = (float*)(sm + SO_RS4);
    float*  inv = (float*)(sm + SO_INV);
    __half* Qs  = (__half*)(sm + SO_Q);
    const uint32_t smb = smem_u32(sm);
    const uint32_t Qb = smb + SO_Q, Xb0 = smb + SO_X0;

    const int tid = threadIdx.x, lane = tid & 31, w = tid >> 5;
    const int b = blockIdx.x >> 5, lt = blockIdx.x & 31, l0 = lt * MQ;
    const size_t bL = (size_t)b * LL;
    const __half* Xg = g_Xh + (size_t)b * TT * HH;

    // labels dtype detection (int64 LE, values < 2^31 => odd words zero)
    int* flag = (int*)(sm + SO_FLAG);
    if (tid == 0) {
        const int* li = (const int*)labels_raw;
        *flag = ((li[1] | li[3] | li[5] | li[7] | li[9] | li[11] | li[13] | li[15]) == 0);
    }
    __syncthreads();
    const bool is64 = (*flag != 0);

    // ---- gather Q (table[labels]) -> fp16 smem (all 512 threads) ----
    {
        const int q = tid >> 3, c0 = (tid & 7) * 4;
        const long long lidx = (long long)b * LL + l0 + q;
        const long long lab = is64 ? ((const long long*)labels_raw)[lidx]
                                   : (long long)((const int*)labels_raw)[lidx];
        const float* row = table + (size_t)lab * HH;
        #pragma unroll
        for (int j = 0; j < 8; j++) {
            const int col = c0 + j * 32;
            float4 v = *(const float4*)(row + col);
            *(half2*)(Qs + q * QP + col)     = __floats2half2_rn(v.x, v.y);
            *(half2*)(Qs + q * QP + col + 2) = __floats2half2_rn(v.z, v.w);
        }
    }
    __syncthreads();

    if (w < 8) {
        // ================= GROUP A: MMA1 + softmax producer =================
        const int wm = w & 3, wn = w >> 2;         // 4M x 2N
        const int m0 = wm * 16;
        const int r = lane >> 2, c2 = (lane & 3) * 2;

        // Q fragments: loop-invariant, register-resident (16 k-steps x 4 regs)
        const uint32_t a1_0 = Qb + (uint32_t)(((m0 + (lane & 15)) * QP + ((lane >> 4) << 3)) * 2);
        uint32_t Aq[64];
        #pragma unroll
        for (int k = 0; k < 16; k++) ldsm4(a1_0 + k * 32, Aq + 4 * k);

        const uint32_t b1r = (uint32_t)(((wn * 32 + (lane & 7) + ((lane >> 4) << 3)) * XP
                                         + ((lane >> 3) & 1) * 8) * 2);
        const int er = tid >> 2, cb = (tid & 3) * 16;
        float rsum0 = 0.f, rsum1 = 0.f;

        for (int i = 0; i < NCHUNK; i++) {
            const uint32_t xcur = Xb0 + (uint32_t)(i % 3) * XCHB;
            bar_sync(1 + i % 3, NTHR);             // X[i] ready (B arrives)

            float sa[4][4];
            #pragma unroll
            for (int j = 0; j < 4; j++)
                sa[j][0] = sa[j][1] = sa[j][2] = sa[j][3] = 0.f;
            #pragma unroll
            for (int k = 0; k < 16; k++) {
                uint32_t Bv[8];
                ldsm4(xcur + b1r + k * 32, Bv);
                ldsm4(xcur + b1r + 16 * XP * 2 + k * 32, Bv + 4);
                mma16816(sa[0], Aq + 4 * k, Bv);
                mma16816(sa[1], Aq + 4 * k, Bv + 2);
                mma16816(sa[2], Aq + 4 * k, Bv + 4);
                mma16816(sa[3], Aq + 4 * k, Bv + 6);
            }
            #pragma unroll
            for (int j = 0; j < 4; j++) {
                sa[j][0] = __expf(sa[j][0]); sa[j][1] = __expf(sa[j][1]);
                sa[j][2] = __expf(sa[j][2]); sa[j][3] = __expf(sa[j][3]);
                rsum0 += sa[j][0] + sa[j][1];
                rsum1 += sa[j][2] + sa[j][3];
            }

            if (i >= 2) bar_sync(6 + (i & 1), NTHR);   // Ec[i&1] free (B arrives)
            __half* Ecb = (__half*)(sm + SO_EC + (size_t)(i & 1) * ECB);
            #pragma unroll
            for (int j = 0; j < 4; j++) {
                const int col = wn * 32 + j * 8 + c2;
                *(half2*)(Ecb + (m0 + r) * ECP + col)     = __floats2half2_rn(sa[j][0], sa[j][1]);
                *(half2*)(Ecb + (m0 + 8 + r) * ECP + col) = __floats2half2_rn(sa[j][2], sa[j][3]);
            }
            __threadfence_block();
            bar_arrive(4 + (i & 1), NTHR);             // Ec[i&1] full
            bar_sync(8, 256);                          // A-internal: all E stored

            // coalesced att write (unnormalized) from Ec
            float* gd = att + (bL + l0 + er) * TT + i * TCHK + cb;
            const __half* es = Ecb + er * ECP + cb;
            #pragma unroll
            for (int j2 = 0; j2 < 4; j2++) {
                float2 f0 = __half22float2(*(const half2*)(es + j2 * 4));
                float2 f1 = __half22float2(*(const half2*)(es + j2 * 4 + 2));
                *(float4*)(gd + j2 * 4) = make_float4(f0.x, f0.y, f1.x, f1.y);
            }
        }

        // row-sum reduce (quad lanes) + publish
        float v0 = rsum0, v1 = rsum1;
        v0 += __shfl_xor_sync(0xffffffffu, v0, 1);
        v0 += __shfl_xor_sync(0xffffffffu, v0, 2);
        v1 += __shfl_xor_sync(0xffffffffu, v1, 1);
        v1 += __shfl_xor_sync(0xffffffffu, v1, 2);
        if ((lane & 3) == 0) {
            rs4[wn * 64 + m0 + r]     = v0;
            rs4[wn * 64 + m0 + 8 + r] = v1;
        }
        bar_sync(10, NTHR);
        if (tid < 64) inv[tid] = 1.0f / (rs4[tid] + rs4[64 + tid]);
        bar_sync(11, NTHR);
    } else {
        // ================= GROUP B: MMA2 consumer + X loader =================
        const int w2 = w - 8, wm2 = w2 & 1, wn2 = w2 >> 1;   // 2M x 4N
        const int r = lane >> 2, c2 = (lane & 3) * 2;
        const int tid2 = tid - 256;
        const int xr = tid2 >> 2, xc = (tid2 & 3) * 64;
        const uint32_t xdst = (uint32_t)((xr * XP + xc) * 2);

        // prime 3 X buffers
        #pragma unroll
        for (int c = 0; c < 3; c++) {
            const __half* src = Xg + (size_t)(c * TCHK + xr) * HH + xc;
            #pragma unroll
            for (int j = 0; j < 8; j++)
                cpasync16(Xb0 + (uint32_t)c * XCHB + xdst + j * 16, src + j * 8);
            CP_COMMIT();
        }

        float o[64];
        #pragma unroll
        for (int i = 0; i < 64; i++) o[i] = 0.f;

        const uint32_t a2base = (uint32_t)(((wm2 * 32 + (lane & 15)) * ECP + ((lane >> 4) << 3)) * 2);
        const uint32_t b2r = (uint32_t)(((lane & 15) * XP + wn2 * 64 + ((lane >> 4) << 3)) * 2);

        for (int i = 0; i < NCHUNK; i++) {
            const uint32_t xcur = Xb0 + (uint32_t)(i % 3) * XCHB;
            CP_WAIT(2);                              // X[i] complete
            __threadfence_block();
            bar_arrive(1 + i % 3, NTHR);             // signal A: X[i] ready
            bar_sync(4 + (i & 1), NTHR);             // Ec[i&1] full (A arrives)

            const uint32_t a2_0 = smb + SO_EC + (uint32_t)(i & 1) * ECB + a2base;
            #pragma unroll
            for (int kst = 0; kst < 4; kst++) {
                uint32_t A0[4], A1[4], Bv[4][4];
                ldsm4(a2_0 + kst * 32, A0);
                ldsm4(a2_0 + 16 * ECP * 2 + kst * 32, A1);
                #pragma unroll
                for (int nb = 0; nb < 4; nb++)
                    ldsm4t(xcur + b2r + kst * 16 * XP * 2 + nb * 32, Bv[nb]);
                #pragma unroll
                for (int nf = 0; nf < 8; nf++) {
                    const uint32_t* bp = &Bv[nf >> 1][(nf & 1) * 2];
                    mma16816(&o[nf * 4],      A0, bp);
                    mma16816(&o[32 + nf * 4], A1, bp);
                }
            }
            bar_arrive(6 + (i & 1), NTHR);           // Ec[i&1] free

            // B-internal drain: ALL B warps must finish their ldsm reads of
            // X[i] before ANY B warp's refill overwrites that ring slot.
            // (r6 bug: per-warp program order only -> slow warps read
            // freshly overwritten rows -> logits corruption.)
            bar_sync(9, 256);

            // refill the X buffer just retired (ring of 3); empty group keeps
            // the wait_group ledger uniform when past the end
            if (i + 3 < NCHUNK) {
                const uint32_t xn = Xb0 + (uint32_t)((i + 3) % 3) * XCHB;
                const __half* src = Xg + (size_t)((i + 3) * TCHK + xr) * HH + xc;
                #pragma unroll
                for (int j = 0; j < 8; j++)
                    cpasync16(xn + xdst + j * 16, src + j * 8);
            }
            CP_COMMIT();
        }

        bar_sync(10, NTHR);
        bar_sync(11, NTHR);                          // inv[] ready

        // write logits (scaled O fragments)
        #pragma unroll
        for (int mt = 0; mt < 2; mt++) {
            const int r0 = wm2 * 32 + mt * 16 + r;
            const float i0 = inv[r0], i1 = inv[r0 + 8];
            float* d0 = logits + (bL + l0 + r0) * HH;
            float* d1 = logits + (bL + l0 + r0 + 8) * HH;
            #pragma unroll
            for (int nf = 0; nf < 8; nf++) {
                const float* ov = &o[mt * 32 + nf * 4];
                const int col = wn2 * 64 + nf * 8 + c2;
                *(float2*)(d0 + col) = make_float2(ov[0] * i0, ov[1] * i0);
                *(float2*)(d1 + col) = make_float2(ov[2] * i1, ov[3] * i1);
            }
        }
    }

    // ---- normalize att in-place (L2-resident RMW; inv[] valid, all threads) ----
    {
        float4* Ab = (float4*)(att + (bL + l0) * TT);
        #pragma unroll 4
        for (int i = tid; i < MQ * TT / 4; i += NTHR) {
            float4 v = Ab[i];
            const float iv = inv[i >> 8];   // 256 float4 per row
            v.x *= iv; v.y *= iv; v.z *= iv; v.w *= iv;
            Ab[i] = v;
        }
    }
}

extern "C" void kernel_launch(void* const* d_in, const int* in_sizes, int n_in,
                              void* d_out, int out_size)
{
    const float* X      = (const float*)d_in[0];
    const void*  labels = d_in[1];
    const float* table  = (const float*)d_in[2];
    float* logits = (float*)d_out;
    float* att    = logits + (size_t)BB * LL * HH;

    xconv<<<(BB * TT * HH) / (256 * 8), 256>>>(X);

    cudaFuncSetAttribute(pla_ws, cudaFuncAttributeMaxDynamicSharedMemorySize, SMEM_BYTES);
    pla_ws<<<BB * (LL / MQ), NTHR, SMEM_BYTES>>>(labels, table, logits, att);
}

// round 9
// speedup vs baseline: 1.0047x; 1.0047x over previous
#include <cuda_runtime.h>
#include <cuda_fp16.h>
#include <cstdint>

#define BB 16
#define TT 1024
#define HH 256
#define LL 2048
#define MQ 64
#define TCHK 64
#define NCHUNK 16
#define NTHR 256

// smem pitches (halves); byte stride = odd multiple of 16B -> conflict-free ldsm
#define QP 264
#define XP 264
#define ECP 72
#define XCHB (TCHK * XP * 2)     // 33792 B per X buffer

// smem byte offsets
#define SO_RS4  0                         // float rs4[4][64]
#define SO_INV  1024                      // float inv[64]
#define SO_FLAG 1280
#define SO_Q    1536                      // 64*264*2 = 33792
#define SO_X0   (SO_Q + 33792)            // 3 X buffers (ring)
#define SO_EC   (SO_X0 + 3 * XCHB)        // single E buffer: 64*72*2 = 9216
#define SMEM_BYTES (SO_EC + 9216)         // 145920 B

__device__ __half g_Xh[(size_t)BB * TT * HH];

__device__ __forceinline__ uint32_t smem_u32(const void* p) {
    uint32_t a;
    asm("{ .reg .u64 t; cvta.to.shared.u64 t, %1; cvt.u32.u64 %0, t; }" : "=r"(a) : "l"(p));
    return a;
}
__device__ __forceinline__ void ldsm4(uint32_t a, uint32_t* r) {
    asm volatile("ldmatrix.sync.aligned.m8n8.x4.shared.b16 {%0,%1,%2,%3}, [%4];"
                 : "=r"(r[0]), "=r"(r[1]), "=r"(r[2]), "=r"(r[3]) : "r"(a));
}
__device__ __forceinline__ void ldsm4t(uint32_t a, uint32_t* r) {
    asm volatile("ldmatrix.sync.aligned.m8n8.x4.trans.shared.b16 {%0,%1,%2,%3}, [%4];"
                 : "=r"(r[0]), "=r"(r[1]), "=r"(r[2]), "=r"(r[3]) : "r"(a));
}
__device__ __forceinline__ void mma16816(float* d, const uint32_t* a, const uint32_t* b) {
    asm volatile("mma.sync.aligned.m16n8k16.row.col.f32.f16.f16.f32 "
                 "{%0,%1,%2,%3}, {%4,%5,%6,%7}, {%8,%9}, {%0,%1,%2,%3};"
                 : "+f"(d[0]), "+f"(d[1]), "+f"(d[2]), "+f"(d[3])
                 : "r"(a[0]), "r"(a[1]), "r"(a[2]), "r"(a[3]), "r"(b[0]), "r"(b[1]));
}
__device__ __forceinline__ void cpasync16(uint32_t sa, const void* ga) {
    asm volatile("cp.async.ca.shared.global [%0], [%1], 16;" :: "r"(sa), "l"(ga));
}
#define CP_COMMIT()  asm volatile("cp.async.commit_group;" ::: "memory")
#define CP_WAIT(n)   asm volatile("cp.async.wait_group %0;" :: "n"(n) : "memory")

// ---------------- X f32 -> fp16 convert ----------------
__global__ void __launch_bounds__(256)
xconv(const float* __restrict__ X)
{
    const size_t i = ((size_t)blockIdx.x * 256 + threadIdx.x) * 8;
    float4 a = *(const float4*)(X + i);
    float4 b = *(const float4*)(X + i + 4);
    half2 h[4] = { __floats2half2_rn(a.x, a.y), __floats2half2_rn(a.z, a.w),
                   __floats2half2_rn(b.x, b.y), __floats2half2_rn(b.z, b.w) };
    *(uint4*)(g_Xh + i) = *(uint4*)h;
}

// ------- main fused kernel: 256 threads, 2Mx4N warps, M=32/warp tiles -------
__global__ void __launch_bounds__(NTHR, 1)
pla_mma(const void*  __restrict__ labels_raw, // (B,L) int32/int64
        const float* __restrict__ table,      // (C+1,H)
        float* __restrict__ logits,           // (B,L,H)
        float* __restrict__ att)              // (B,L,T)
{
    extern __shared__ char sm[];
    float*  rs4 = (float*)(sm + SO_RS4);
    float*  inv = (float*)(sm + SO_INV);
    __half* Qs  = (__half*)(sm + SO_Q);
    __half* Ec  = (__half*)(sm + SO_EC);
    const uint32_t smb = smem_u32(sm);
    const uint32_t Qb = smb + SO_Q, Xb0 = smb + SO_X0, Eb = smb + SO_EC;

    const int tid = threadIdx.x, lane = tid & 31, w = tid >> 5;
    const int wm = w & 1, wn = w >> 1;       // 2(M) x 4(N)
    const int m0 = wm * 32;
    const int b = blockIdx.x >> 5, lt = blockIdx.x & 31, l0 = lt * MQ;
    const size_t bL = (size_t)b * LL;
    const __half* Xg = g_Xh + (size_t)b * TT * HH;

    // cp.async geometry: 4 threads/row, 8 x 16B each
    const int xr = tid >> 2, xc = (tid & 3) * 64;
    const uint32_t xdst = (uint32_t)((xr * XP + xc) * 2);

    // ---- prime X[0], X[1] (overlaps flag + Q gather) ----
    #pragma unroll
    for (int c = 0; c < 2; c++) {
        const __half* src = Xg + (size_t)(c * TCHK + xr) * HH + xc;
        #pragma unroll
        for (int j = 0; j < 8; j++)
            cpasync16(Xb0 + (uint32_t)c * XCHB + xdst + j * 16, src + j * 8);
        CP_COMMIT();
    }

    // labels dtype detection (int64 LE, values < 2^31 => odd words zero)
    int* flag = (int*)(sm + SO_FLAG);
    if (tid == 0) {
        const int* li = (const int*)labels_raw;
        *flag = ((li[1] | li[3] | li[5] | li[7] | li[9] | li[11] | li[13] | li[15]) == 0);
    }
    __syncthreads();
    const bool is64 = (*flag != 0);

    // ---- gather Q (table[labels]) -> fp16 smem ----
    {
        const int q = tid >> 2, c0 = (tid & 3) * 4;
        const long long lidx = (long long)b * LL + l0 + q;
        const long long lab = is64 ? ((const long long*)labels_raw)[lidx]
                                   : (long long)((const int*)labels_raw)[lidx];
        const float* row = table + (size_t)lab * HH;
        #pragma unroll
        for (int j = 0; j < 16; j++) {
            const int col = c0 + j * 16;
            float4 v = *(const float4*)(row + col);
            *(half2*)(Qs + q * QP + col)     = __floats2half2_rn(v.x, v.y);
            *(half2*)(Qs + q * QP + col + 2) = __floats2half2_rn(v.z, v.w);
        }
    }
    // Q visibility to all warps is guaranteed by the chunk-0 sync below.

    float rsum[4] = {0.f, 0.f, 0.f, 0.f};
    float o[64];
    #pragma unroll
    for (int i = 0; i < 64; i++) o[i] = 0.f;

    const uint32_t a1_0 = Qb + (uint32_t)(((m0 + (lane & 15)) * QP + ((lane >> 4) << 3)) * 2);
    const uint32_t b1r  = (uint32_t)(((wn * 16 + (lane & 7) + ((lane >> 4) << 3)) * XP
                                      + ((lane >> 3) & 1) * 8) * 2);
    const uint32_t a2_0 = Eb + (uint32_t)(((m0 + (lane & 15)) * ECP + ((lane >> 4) << 3)) * 2);
    const uint32_t b2r  = (uint32_t)(((lane & 15) * XP + wn * 64 + ((lane >> 4) << 3)) * 2);

    const int r = lane >> 2, c2 = (lane & 3) * 2;
    const int er = tid >> 2, cb = (tid & 3) * 16;

    for (int i = 0; i < NCHUNK; i++) {
        const uint32_t xcur = Xb0 + (uint32_t)(i % 3) * XCHB;

        CP_WAIT(1);          // X[i] landed (X[i+1] may still be in flight)
        __syncthreads();     // sync-1: X[i] visible; also fences prior-chunk
                             // MMA2/att reads of Ec before this chunk's writes

        // ---- MMA1: S[32x16 per warp] = Q * Xchunk^T (K = 256) ----
        float sa[4][4];
        #pragma unroll
        for (int j = 0; j < 4; j++)
            sa[j][0] = sa[j][1] = sa[j][2] = sa[j][3] = 0.f;
        #pragma unroll 4
        for (int k = 0; k < 16; k++) {
            uint32_t A0[4], A1[4], Bv[4];
            ldsm4(a1_0 + k * 32, A0);
            ldsm4(a1_0 + 16 * QP * 2 + k * 32, A1);
            ldsm4(xcur + b1r + k * 32, Bv);
            mma16816(sa[0], A0, Bv);
            mma16816(sa[1], A0, Bv + 2);
            mma16816(sa[2], A1, Bv);
            mma16816(sa[3], A1, Bv + 2);
        }

        // ---- epilogue: e = exp(s) -> Ec fp16 + running row sums ----
        // sa[j]: rows m0 + (j>>1)*16 + {r, r+8}, cols wn*16 + (j&1)*8 + c2
        #pragma unroll
        for (int j = 0; j < 4; j++) {
            float* s = sa[j];
            const float e0 = __expf(s[0]), e1 = __expf(s[1]);
            const float e2 = __expf(s[2]), e3 = __expf(s[3]);
            rsum[(j >> 1) * 2 + 0] += e0 + e1;
            rsum[(j >> 1) * 2 + 1] += e2 + e3;
            const int ra  = m0 + (j >> 1) * 16 + r;
            const int col = wn * 16 + (j & 1) * 8 + c2;
            *(half2*)(Ec + ra * ECP + col)       = __floats2half2_rn(e0, e1);
            *(half2*)(Ec + (ra + 8) * ECP + col) = __floats2half2_rn(e2, e3);
        }
        __syncthreads();     // sync-2: Ec full; all MMA1 reads of X done

        // refill retired ring slot (held X[i-1]; its last readers — MMA2(i-1) —
        // are ordered before this point by sync-1 of this chunk)
        if (i + 2 < NCHUNK) {
            const uint32_t xn = Xb0 + (uint32_t)((i + 2) % 3) * XCHB;
            const __half* src = Xg + (size_t)((i + 2) * TCHK + xr) * HH + xc;
            #pragma unroll
            for (int j = 0; j < 8; j++)
                cpasync16(xn + xdst + j * 16, src + j * 8);
        }
        CP_COMMIT();

        // ---- MMA2: O[32x64 per warp] += E[32x64] * Xchunk slice ----
        #pragma unroll
        for (int kst = 0; kst < 4; kst++) {
            uint32_t A0[4], A1[4], Bv[4][4];
            ldsm4(a2_0 + kst * 32, A0);
            ldsm4(a2_0 + 16 * ECP * 2 + kst * 32, A1);
            #pragma unroll
            for (int nb = 0; nb < 4; nb++)
                ldsm4t(xcur + b2r + kst * 16 * XP * 2 + nb * 32, Bv[nb]);
            #pragma unroll
            for (int nf = 0; nf < 8; nf++) {
                const uint32_t* bp = &Bv[nf >> 1][(nf & 1) * 2];
                mma16816(&o[nf * 4],      A0, bp);
                mma16816(&o[32 + nf * 4], A1, bp);
            }
        }

        // ---- write unnormalized E chunk to att gmem (coalesced) ----
        {
            float* gd = att + (bL + l0 + er) * TT + i * TCHK + cb;
            const __half* es = Ec + er * ECP + cb;
            #pragma unroll
            for (int j2 = 0; j2 < 4; j2++) {
                float2 f0 = __half22float2(*(const half2*)(es + j2 * 4));
                float2 f1 = __half22float2(*(const half2*)(es + j2 * 4 + 2));
                *(float4*)(gd + j2 * 4) = make_float4(f0.x, f0.y, f1.x, f1.y);
            }
        }
    }

    // ---- reduce row sums across quad lanes, publish, compute inverses ----
    #pragma unroll
    for (int s = 0; s < 4; s++) {
        float v = rsum[s];
        v += __shfl_xor_sync(0xffffffffu, v, 1);
        v += __shfl_xor_sync(0xffffffffu, v, 2);
        if ((lane & 3) == 0)
            rs4[wn * 64 + m0 + (s >> 1) * 16 + (s & 1) * 8 + r] = v;
    }
    __syncthreads();
    if (tid < 64)
        inv[tid] = 1.0f / (rs4[tid] + rs4[64 + tid] + rs4[128 + tid] + rs4[192 + tid]);
    __syncthreads();

    // ---- write logits (scaled O fragments) ----
    #pragma unroll
    for (int mf = 0; mf < 2; mf++) {
        const int r0 = m0 + mf * 16 + r;
        const float i0 = inv[r0], i1 = inv[r0 + 8];
        float* d0 = logits + (bL + l0 + r0) * HH;
        float* d1 = logits + (bL + l0 + r0 + 8) * HH;
        #pragma unroll
        for (int nf = 0; nf < 8; nf++) {
            const float* ov = &o[mf * 32 + nf * 4];
            const int col = wn * 64 + nf * 8 + c2;
            *(float2*)(d0 + col) = make_float2(ov[0] * i0, ov[1] * i0);
            *(float2*)(d1 + col) = make_float2(ov[2] * i1, ov[3] * i1);
        }
    }

    // ---- normalize att in-place (L2-resident RMW) ----
    {
        float4* Ab = (float4*)(att + (bL + l0) * TT);
        #pragma unroll 4
        for (int i = tid; i < MQ * TT / 4; i += NTHR) {
            float4 v = Ab[i];
            const float iv = inv[i >> 8];   // 256 float4 per row
            v.x *= iv; v.y *= iv; v.z *= iv; v.w *= iv;
            Ab[i] = v;
        }
    }
}

extern "C" void kernel_launch(void* const* d_in, const int* in_sizes, int n_in,
                              void* d_out, int out_size)
{
    const float* X      = (const float*)d_in[0];
    const void*  labels = d_in[1];
    const float* table  = (const float*)d_in[2];
    float* logits = (float*)d_out;
    float* att    = logits + (size_t)BB * LL * HH;

    xconv<<<(BB * TT * HH) / (256 * 8), 256>>>(X);

    cudaFuncSetAttribute(pla_mma, cudaFuncAttributeMaxDynamicSharedMemorySize, SMEM_BYTES);
    pla_mma<<<BB * (LL / MQ), NTHR, SMEM_BYTES>>>(labels, table, logits, att);
}